// round 4
// baseline (speedup 1.0000x reference)
#include <cuda_runtime.h>
#include <math.h>
#include <stdint.h>

// Problem shape (fixed): query [4096,1024] f32, memory [8192,1024] f32, k=16 (int).
#define D    1024
#define MAXB 4096
#define MAXM 8192
#define KMAX 32
#define NCAND 32          // fp32 candidates per row, rescored exactly in fp64

// SGEMM tile config: 128x128 block tile, BK=8, 256 threads, 8x8 per-thread microtile.
#define BM 128
#define BN 128
#define BK 8

__device__ float  g_sim[(size_t)MAXB * MAXM];   // 128 MB scratch (device global: allowed)
__device__ float  g_qinv[MAXB];
__device__ float  g_minv[MAXM];
__device__ double g_qn2[MAXB];                  // fp64 sum-of-squares (exact norms)
__device__ double g_mn2[MAXM];

__device__ __forceinline__ float neg_inf() { return -__int_as_float(0x7f800000); }

// ---------------------------------------------------------------------------
// Kernel 1: per-row sum of squares in fp64 (for exact rescoring) + fp32
// inverse norms (for the fast GEMM). Blocks [0,B) -> query, [B,B+M) -> memory.
// ---------------------------------------------------------------------------
__global__ __launch_bounds__(128) void norms_kernel(const float* __restrict__ q,
                                                    const float* __restrict__ m,
                                                    int B, int M) {
    int r = blockIdx.x;
    const float* src;
    float*  finv;
    double* dn2;
    if (r < B) { src = q + (size_t)r * D;        finv = g_qinv + r;       dn2 = g_qn2 + r; }
    else       { src = m + (size_t)(r - B) * D;  finv = g_minv + (r - B); dn2 = g_mn2 + (r - B); }

    int t = threadIdx.x;
    double s = 0.0;
    #pragma unroll
    for (int i = t * 4; i < D; i += 128 * 4) {
        float4 v = *(const float4*)(src + i);
        s += (double)v.x * v.x + (double)v.y * v.y
           + (double)v.z * v.z + (double)v.w * v.w;
    }
    #pragma unroll
    for (int o = 16; o; o >>= 1) s += __shfl_down_sync(0xffffffffu, s, o);

    __shared__ double red[4];
    if ((t & 31) == 0) red[t >> 5] = s;
    __syncthreads();
    if (t == 0) {
        double tot = red[0] + red[1] + red[2] + red[3];
        *dn2  = tot;
        *finv = 1.0f / fmaxf(sqrtf((float)tot), 1e-12f);
    }
}

// ---------------------------------------------------------------------------
// Kernel 2: fp32 SGEMM  sim[b,m] = dot(Q[b,:], Mem[m,:]) * qinv[b] * minv[m]
// 128x128 tile / 256 threads / 8x8 microtile / BK=8, double-buffered smem.
// Only needs to be accurate enough that true top-16 lands in fp32 top-32
// (margin ~5 orders of magnitude).
// ---------------------------------------------------------------------------
__global__ __launch_bounds__(256) void gemm_kernel(const float* __restrict__ Q,
                                                   const float* __restrict__ Mem,
                                                   int B, int M) {
    __shared__ float As[2][BK][BM];
    __shared__ float Bs[2][BK][BN];

    const int t = threadIdx.x;
    const int rowBase = blockIdx.y * BM;
    const int colBase = blockIdx.x * BN;

    const int lr = t >> 1;            // 0..127 : tile row loaded
    const int lk = (t & 1) << 2;      // 0 or 4 : k offset

    const int tx = (t & 15) << 3;     // output col offset (0..120)
    const int ty = (t >> 4) << 3;     // output row offset

    const float* aptr = Q   + (size_t)(rowBase + lr) * D + lk;
    const float* bptr = Mem + (size_t)(colBase + lr) * D + lk;

    float acc[8][8];
    #pragma unroll
    for (int i = 0; i < 8; i++)
        #pragma unroll
        for (int j = 0; j < 8; j++) acc[i][j] = 0.f;

    const int NT = D / BK;

    {
        float4 av = *(const float4*)(aptr);
        float4 bv = *(const float4*)(bptr);
        As[0][lk + 0][lr] = av.x; As[0][lk + 1][lr] = av.y;
        As[0][lk + 2][lr] = av.z; As[0][lk + 3][lr] = av.w;
        Bs[0][lk + 0][lr] = bv.x; Bs[0][lk + 1][lr] = bv.y;
        Bs[0][lk + 2][lr] = bv.z; Bs[0][lk + 3][lr] = bv.w;
    }
    __syncthreads();

    int buf = 0;
    for (int kt = 0; kt < NT; kt++) {
        float4 an, bn;
        const bool more = (kt + 1 < NT);
        if (more) {
            an = *(const float4*)(aptr + (kt + 1) * BK);
            bn = *(const float4*)(bptr + (kt + 1) * BK);
        }

        #pragma unroll
        for (int k = 0; k < BK; k++) {
            float4 a0 = *(const float4*)&As[buf][k][ty];
            float4 a1 = *(const float4*)&As[buf][k][ty + 4];
            float4 b0 = *(const float4*)&Bs[buf][k][tx];
            float4 b1 = *(const float4*)&Bs[buf][k][tx + 4];
            float ar[8] = {a0.x, a0.y, a0.z, a0.w, a1.x, a1.y, a1.z, a1.w};
            float br[8] = {b0.x, b0.y, b0.z, b0.w, b1.x, b1.y, b1.z, b1.w};
            #pragma unroll
            for (int i = 0; i < 8; i++)
                #pragma unroll
                for (int j = 0; j < 8; j++)
                    acc[i][j] += ar[i] * br[j];
        }

        if (more) {
            int nb = buf ^ 1;
            As[nb][lk + 0][lr] = an.x; As[nb][lk + 1][lr] = an.y;
            As[nb][lk + 2][lr] = an.z; As[nb][lk + 3][lr] = an.w;
            Bs[nb][lk + 0][lr] = bn.x; Bs[nb][lk + 1][lr] = bn.y;
            Bs[nb][lk + 2][lr] = bn.z; Bs[nb][lk + 3][lr] = bn.w;
            __syncthreads();
        }
        buf ^= 1;
    }

    float qi[8], mi[8];
    #pragma unroll
    for (int i = 0; i < 8; i++) qi[i] = g_qinv[rowBase + ty + i];
    #pragma unroll
    for (int j = 0; j < 8; j++) mi[j] = g_minv[colBase + tx + j];

    #pragma unroll
    for (int i = 0; i < 8; i++) {
        float* orow = &g_sim[(size_t)(rowBase + ty + i) * M + colBase + tx];
        float4 o0, o1;
        o0.x = acc[i][0] * qi[i] * mi[0];
        o0.y = acc[i][1] * qi[i] * mi[1];
        o0.z = acc[i][2] * qi[i] * mi[2];
        o0.w = acc[i][3] * qi[i] * mi[3];
        o1.x = acc[i][4] * qi[i] * mi[4];
        o1.y = acc[i][5] * qi[i] * mi[5];
        o1.z = acc[i][6] * qi[i] * mi[6];
        o1.w = acc[i][7] * qi[i] * mi[7];
        __stcs((float4*)(orow),     o0);
        __stcs((float4*)(orow + 4), o1);
    }
}

// ---------------------------------------------------------------------------
// Kernel 3: per query row
//   (a) mask sim==1.0 -> -inf, select top-NCAND candidates by fp32 value
//   (b) rescore candidates EXACTLY: fp64 dot / (fp64 norms) -> true ordering
//   (c) pick top-k among candidates by fp64 value (ties -> lowest index)
//   (d) out[b,:] = sum_k w_k * Mem[idx_k,:]  (non-finite weights zeroed)
// One 256-thread block per row.
// ---------------------------------------------------------------------------
__global__ __launch_bounds__(256) void topk_kernel(const float* __restrict__ Q,
                                                   const float* __restrict__ Mem,
                                                   float* __restrict__ out,
                                                   const int* __restrict__ kp,
                                                   int B, int M) {
    __shared__ float  sv[MAXM];       // 32 KB
    __shared__ float  redv[256];
    __shared__ int    redi[256];
    __shared__ int    cidx[NCAND];
    __shared__ double cval[NCAND];
    __shared__ float  qs[D];          // 4 KB
    __shared__ float  fw[KMAX];
    __shared__ int    fi[KMAX];

    int b = blockIdx.x;
    int t = threadIdx.x;
    const float* row = g_sim + (size_t)b * M;

    // --- load sims, mask ==1.0 ---
    for (int i = t * 4; i < M; i += 256 * 4) {
        float4 v = __ldcs((const float4*)(row + i));
        if (v.x == 1.0f) v.x = neg_inf();
        if (v.y == 1.0f) v.y = neg_inf();
        if (v.z == 1.0f) v.z = neg_inf();
        if (v.w == 1.0f) v.w = neg_inf();
        *(float4*)&sv[i] = v;
    }
    // also stage the query row for rescoring
    for (int i = t; i < D; i += 256) qs[i] = Q[(size_t)b * D + i];
    __syncthreads();

    // --- (a) top-NCAND candidates by fp32 (iterative block argmax) ---
    for (int it = 0; it < NCAND; it++) {
        float bv = neg_inf();
        int bi = 0x7fffffff;
        for (int i = t; i < M; i += 256) {
            float v = sv[i];
            if (v > bv) { bv = v; bi = i; }       // strict > keeps lowest index
        }
        redv[t] = bv; redi[t] = bi;
        __syncthreads();
        #pragma unroll
        for (int s2 = 128; s2 > 0; s2 >>= 1) {
            if (t < s2) {
                float ov = redv[t + s2];
                int   oi = redi[t + s2];
                if (ov > redv[t] || (ov == redv[t] && oi < redi[t])) {
                    redv[t] = ov; redi[t] = oi;
                }
            }
            __syncthreads();
        }
        if (t == 0) {
            cidx[it] = redi[0];
            if (redi[0] < M) sv[redi[0]] = neg_inf();
        }
        __syncthreads();
    }

    // --- (b) exact fp64 rescore: one warp per candidate, round-robin ---
    {
        int warp = t >> 5, lane = t & 31;
        double qn = sqrt(g_qn2[b]);
        double qd = fmax(qn, 1e-12);
        for (int c = warp; c < NCAND; c += 8) {
            int idx = cidx[c];
            const float* mrow = Mem + (size_t)idx * D;
            double acc = 0.0;
            #pragma unroll 4
            for (int d = lane; d < D; d += 32)
                acc += (double)qs[d] * (double)mrow[d];
            #pragma unroll
            for (int o = 16; o; o >>= 1) acc += __shfl_down_sync(0xffffffffu, acc, o);
            if (lane == 0) {
                double md = fmax(sqrt(g_mn2[idx]), 1e-12);
                cval[c] = acc / (qd * md);
            }
        }
    }
    __syncthreads();

    int k = *kp;
    if (k > KMAX)  k = KMAX;
    if (k > NCAND) k = NCAND;
    if (k > M)     k = M;

    // --- (c) top-k among the NCAND exact values (serial, tiny) ---
    if (t == 0) {
        unsigned used = 0u;
        for (int it = 0; it < k; it++) {
            double bv = -1e300;
            int bc = -1, bidx = 0x7fffffff;
            for (int c = 0; c < NCAND; c++) {
                if (used & (1u << c)) continue;
                double v = cval[c];
                int   ix = cidx[c];
                if (v > bv || (v == bv && ix < bidx)) { bv = v; bc = c; bidx = ix; }
            }
            used |= (1u << bc);
            float wv = (float)bv;
            if (!isfinite(wv)) wv = 0.f;
            fw[it] = wv;
            fi[it] = bidx;
        }
    }
    __syncthreads();

    // --- (d) weighted sum of ORIGINAL memory rows ---
    for (int d = t; d < D; d += 256) {
        float acc = 0.f;
        for (int j = 0; j < k; j++)
            acc += fw[j] * Mem[(size_t)fi[j] * D + d];
        out[(size_t)b * D + d] = acc;
    }
}

// ---------------------------------------------------------------------------
extern "C" void kernel_launch(void* const* d_in, const int* in_sizes, int n_in,
                              void* d_out, int out_size) {
    const float* q  = (const float*)d_in[0];
    const float* m  = (const float*)d_in[1];
    const int*   kp = (const int*)d_in[2];
    float* out = (float*)d_out;

    int B = in_sizes[0] / D;   // 4096
    int M = in_sizes[1] / D;   // 8192

    norms_kernel<<<B + M, 128>>>(q, m, B, M);

    dim3 gg(M / BN, B / BM);
    gemm_kernel<<<gg, 256>>>(q, m, B, M);

    topk_kernel<<<B, 256>>>(q, m, out, kp, B, M);
}

// round 5
// speedup vs baseline: 2.2541x; 2.2541x over previous
#include <cuda_runtime.h>
#include <cuda_bf16.h>
#include <math.h>
#include <stdint.h>

// Problem shape (fixed): query [4096,1024] f32, memory [8192,1024] f32, k=16.
#define D     1024
#define MAXB  4096
#define MAXM  8192
#define KMAX  32
#define NCAND 48        // bf16-GEMM candidates per row, rescored exactly in fp64

// HGEMM tile config
#define BM  128
#define BN  128
#define BKH 32          // bf16 k per tile (64 bytes per row)

__device__ float  g_sim[(size_t)MAXB * MAXM];   // 128 MB scratch
__device__ float  g_qinv[MAXB];
__device__ float  g_minv[MAXM];
__device__ double g_qn2[MAXB];
__device__ double g_mn2[MAXM];
__device__ __nv_bfloat16 g_qb[(size_t)MAXB * D];  // pre-normalized bf16 query
__device__ __nv_bfloat16 g_mb[(size_t)MAXM * D];  // pre-normalized bf16 memory

__device__ __forceinline__ float neg_inf() { return -__int_as_float(0x7f800000); }

__device__ __forceinline__ unsigned fkey(float f) {  // order-preserving float->u32
    unsigned u = __float_as_uint(f);
    return (u & 0x80000000u) ? ~u : (u | 0x80000000u);
}

__device__ __forceinline__ uint32_t smem_u32(const void* p) {
    return (uint32_t)__cvta_generic_to_shared(p);
}

#define CP16(dst, src) asm volatile("cp.async.cg.shared.global [%0], [%1], 16;\n" :: "r"(dst), "l"(src))
#define CP_COMMIT()    asm volatile("cp.async.commit_group;\n")
#define CP_WAIT(n)     asm volatile("cp.async.wait_group %0;\n" :: "n"(n))

__device__ __forceinline__ void ldsm_x4(uint32_t* r, uint32_t addr) {
    asm volatile("ldmatrix.sync.aligned.m8n8.x4.shared.b16 {%0,%1,%2,%3}, [%4];"
                 : "=r"(r[0]), "=r"(r[1]), "=r"(r[2]), "=r"(r[3]) : "r"(addr));
}
__device__ __forceinline__ void ldsm_x2(uint32_t* r, uint32_t addr) {
    asm volatile("ldmatrix.sync.aligned.m8n8.x2.shared.b16 {%0,%1}, [%2];"
                 : "=r"(r[0]), "=r"(r[1]) : "r"(addr));
}
__device__ __forceinline__ void mma16816(float* c, const uint32_t* a, const uint32_t* b) {
    asm volatile("mma.sync.aligned.m16n8k16.row.col.f32.bf16.bf16.f32 "
                 "{%0,%1,%2,%3}, {%4,%5,%6,%7}, {%8,%9}, {%0,%1,%2,%3};"
                 : "+f"(c[0]), "+f"(c[1]), "+f"(c[2]), "+f"(c[3])
                 : "r"(a[0]), "r"(a[1]), "r"(a[2]), "r"(a[3]), "r"(b[0]), "r"(b[1]));
}

// smem tile layout: row stride 64B, 4 chunks of 16B, swizzled c' = c ^ (row&3)
__device__ __forceinline__ uint32_t tile_off(int row, int c) {
    return (uint32_t)(row * 64 + ((c ^ (row & 3)) << 4));
}

// ---------------------------------------------------------------------------
// Kernel 1: fp64 sum-of-squares + fp32 inverse norms per row.
// ---------------------------------------------------------------------------
__global__ __launch_bounds__(128) void norms_kernel(const float* __restrict__ q,
                                                    const float* __restrict__ m,
                                                    int B, int M) {
    int r = blockIdx.x;
    const float* src;
    float*  finv;
    double* dn2;
    if (r < B) { src = q + (size_t)r * D;        finv = g_qinv + r;       dn2 = g_qn2 + r; }
    else       { src = m + (size_t)(r - B) * D;  finv = g_minv + (r - B); dn2 = g_mn2 + (r - B); }

    int t = threadIdx.x;
    double s = 0.0;
    #pragma unroll
    for (int i = t * 4; i < D; i += 128 * 4) {
        float4 v = *(const float4*)(src + i);
        s += (double)v.x * v.x + (double)v.y * v.y
           + (double)v.z * v.z + (double)v.w * v.w;
    }
    #pragma unroll
    for (int o = 16; o; o >>= 1) s += __shfl_down_sync(0xffffffffu, s, o);

    __shared__ double red[4];
    if ((t & 31) == 0) red[t >> 5] = s;
    __syncthreads();
    if (t == 0) {
        double tot = red[0] + red[1] + red[2] + red[3];
        *dn2  = tot;
        *finv = 1.0f / fmaxf(sqrtf((float)tot), 1e-12f);
    }
}

// ---------------------------------------------------------------------------
// Kernel 2: convert rows to pre-normalized bf16 (inverse norm folded in).
// ---------------------------------------------------------------------------
__global__ __launch_bounds__(256) void convert_kernel(const float* __restrict__ q,
                                                      const float* __restrict__ m,
                                                      int B, int M) {
    int r = blockIdx.x;
    const float* src;
    __nv_bfloat16* dst;
    float inv;
    if (r < B) { src = q + (size_t)r * D;       dst = g_qb + (size_t)r * D;       inv = g_qinv[r]; }
    else       { src = m + (size_t)(r - B) * D; dst = g_mb + (size_t)(r - B) * D; inv = g_minv[r - B]; }

    int t = threadIdx.x;
    for (int i = t * 4; i < D; i += 256 * 4) {
        float4 v = *(const float4*)(src + i);
        __nv_bfloat162 lo = __floats2bfloat162_rn(v.x * inv, v.y * inv);
        __nv_bfloat162 hi = __floats2bfloat162_rn(v.z * inv, v.w * inv);
        *(__nv_bfloat162*)(dst + i)     = lo;
        *(__nv_bfloat162*)(dst + i + 2) = hi;
    }
}

// ---------------------------------------------------------------------------
// Kernel 3: bf16 tensor-core GEMM  sim = Qn @ Mn^T  (fp32 accum).
// 128x128 tile, BK=32, 256 threads (8 warps as 2m x 4n), cp.async double buffer.
// ---------------------------------------------------------------------------
__global__ __launch_bounds__(256) void hgemm_kernel(int B, int M) {
    __shared__ __align__(128) uint8_t sA[2][BM * 64];  // 8 KB per buffer
    __shared__ __align__(128) uint8_t sB[2][BN * 64];

    const int t = threadIdx.x;
    const int warp = t >> 5, lane = t & 31;
    const int warp_m = warp >> 2;     // 0..1 -> 64-row slab
    const int warp_n = warp & 3;      // 0..3 -> 32-col slab
    const int rowBase = blockIdx.y * BM;
    const int colBase = blockIdx.x * BN;

    // cp.async mapping: thread t loads row t/2, chunks (t&1)*2 .. +1 (16B each)
    const int ldrow = t >> 1;
    const int ldc0  = (t & 1) * 2;
    const uint32_t abase[2] = { smem_u32(sA[0]), smem_u32(sA[1]) };
    const uint32_t bbase[2] = { smem_u32(sB[0]), smem_u32(sB[1]) };
    const uint32_t off0 = tile_off(ldrow, ldc0);
    const uint32_t off1 = tile_off(ldrow, ldc0 + 1);

    const __nv_bfloat16* agp = g_qb + (size_t)(rowBase + ldrow) * D + ldc0 * 8;
    const __nv_bfloat16* bgp = g_mb + (size_t)(colBase + ldrow) * D + ldc0 * 8;

    float acc[4][4][4];
    #pragma unroll
    for (int i = 0; i < 4; i++)
        #pragma unroll
        for (int j = 0; j < 4; j++)
            #pragma unroll
            for (int x = 0; x < 4; x++) acc[i][j][x] = 0.f;

    const int NT = D / BKH;   // 32 K-tiles

    // preload tile 0 into buffer 0
    CP16(abase[0] + off0, agp);      CP16(abase[0] + off1, agp + 8);
    CP16(bbase[0] + off0, bgp);      CP16(bbase[0] + off1, bgp + 8);
    CP_COMMIT();

    // per-thread ldmatrix source addresses (row part is lane-invariant per tile)
    // A x4: mats: lane/8 = 0:(r,+kc0) 1:(r+8,kc0) 2:(r,kc0+1) 3:(r+8,kc0+1)
    const int a_r   = warp_m * 64 + (lane & 7) + ((lane >> 3) & 1) * 8;  // + mi*16
    const int a_kc  = (lane >> 4);                                       // + 2*ks
    // B x2: lanes 0-7 -> (n, kc0), 8-15 -> (n, kc0+1)
    const int b_li  = lane & 15;
    const int b_r   = warp_n * 32 + (b_li & 7);                          // + nj*8
    const int b_kc  = (b_li >> 3);                                       // + 2*ks

    int buf = 0;
    for (int kt = 0; kt < NT; kt++) {
        if (kt + 1 < NT) {
            const __nv_bfloat16* an = agp + (kt + 1) * BKH;
            const __nv_bfloat16* bn = bgp + (kt + 1) * BKH;
            int nb = buf ^ 1;
            CP16(abase[nb] + off0, an);      CP16(abase[nb] + off1, an + 8);
            CP16(bbase[nb] + off0, bn);      CP16(bbase[nb] + off1, bn + 8);
            CP_COMMIT();
            CP_WAIT(1);
        } else {
            CP_WAIT(0);
        }
        __syncthreads();

        #pragma unroll
        for (int ks = 0; ks < 2; ks++) {          // two k16 steps per 32-wide tile
            uint32_t af[4][4];
            #pragma unroll
            for (int mi = 0; mi < 4; mi++) {
                int r  = a_r + mi * 16;
                int kc = 2 * ks + a_kc;
                ldsm_x4(af[mi], abase[buf] + tile_off(r, kc));
            }
            uint32_t bfr[4][2];
            #pragma unroll
            for (int nj = 0; nj < 4; nj++) {
                int r  = b_r + nj * 8;
                int kc = 2 * ks + b_kc;
                ldsm_x2(bfr[nj], bbase[buf] + tile_off(r, kc));
            }
            #pragma unroll
            for (int mi = 0; mi < 4; mi++)
                #pragma unroll
                for (int nj = 0; nj < 4; nj++)
                    mma16816(acc[mi][nj], af[mi], bfr[nj]);
        }
        __syncthreads();
        buf ^= 1;
    }

    // epilogue: write fp32 sims (streaming)
    const int gid = lane >> 2;    // 0..7  (row within 8)
    const int qid = lane & 3;     // 0..3  (col pair)
    #pragma unroll
    for (int mi = 0; mi < 4; mi++) {
        #pragma unroll
        for (int nj = 0; nj < 4; nj++) {
            int r0 = rowBase + warp_m * 64 + mi * 16 + gid;
            int c0 = colBase + warp_n * 32 + nj * 8 + qid * 2;
            float2 v0 = make_float2(acc[mi][nj][0], acc[mi][nj][1]);
            float2 v1 = make_float2(acc[mi][nj][2], acc[mi][nj][3]);
            __stcs((float2*)&g_sim[(size_t)r0 * M + c0], v0);
            __stcs((float2*)&g_sim[(size_t)(r0 + 8) * M + c0], v1);
        }
    }
}

// ---------------------------------------------------------------------------
// Kernel 4: per query row
//   (a) cached hierarchical argmax extracts top-NCAND candidate indices
//   (b) exact fp64 rescore of candidates (true cosine ordering)
//   (c) top-k among candidates by fp64 value (==1.0 masked; ties -> low index)
//   (d) out[b,:] = sum_k w_k * Mem[idx_k,:]
// ---------------------------------------------------------------------------
__global__ __launch_bounds__(256) void topk_kernel(const float* __restrict__ Q,
                                                   const float* __restrict__ Mem,
                                                   float* __restrict__ out,
                                                   const int* __restrict__ kp,
                                                   int B, int M) {
    __shared__ float sv[MAXM];                        // 32 KB
    __shared__ unsigned long long wmax[8];
    __shared__ unsigned long long s_win;
    __shared__ int    cidx[NCAND];
    __shared__ double cval[NCAND];
    __shared__ float  qs[D];                          // 4 KB
    __shared__ float  fw[KMAX];
    __shared__ int    fi[KMAX];

    const int b = blockIdx.x;
    const int t = threadIdx.x;
    const int warp = t >> 5, lane = t & 31;
    const float* row = g_sim + (size_t)b * M;

    for (int i = t * 4; i < M; i += 256 * 4) {
        float4 v = __ldcs((const float4*)(row + i));
        *(float4*)&sv[i] = v;
    }
    for (int i = t; i < D; i += 256) qs[i] = Q[(size_t)b * D + i];
    __syncthreads();

    // per-thread max over owned strided elements (key = ordered-val || ~idx)
    unsigned long long mykey = 0ull;
    for (int i = t; i < M; i += 256) {
        unsigned long long kk = ((unsigned long long)fkey(sv[i]) << 32)
                              | (unsigned)(0xFFFFFFFFu - (unsigned)i);
        if (kk > mykey) mykey = kk;
    }
    {
        unsigned long long kk = mykey;
        #pragma unroll
        for (int o = 16; o; o >>= 1) {
            unsigned long long ot = __shfl_down_sync(0xffffffffu, kk, o);
            if (ot > kk) kk = ot;
        }
        if (lane == 0) wmax[warp] = kk;
    }
    __syncthreads();

    // extract NCAND maxima
    for (int it = 0; it < NCAND; it++) {
        if (warp == 0 && lane < 8) {
            unsigned long long kk = wmax[lane];
            #pragma unroll
            for (int o = 4; o; o >>= 1) {
                unsigned long long ot = __shfl_down_sync(0xffu, kk, o);
                if (ot > kk) kk = ot;
            }
            if (lane == 0) s_win = kk;
        }
        __syncthreads();
        unsigned widx = 0xFFFFFFFFu - (unsigned)s_win;
        if (t == 0) cidx[it] = (int)widx;
        int owner = (int)(widx & 255u);
        if (t == owner) {
            sv[widx] = neg_inf();
            unsigned long long nk = 0ull;
            for (int i = t; i < M; i += 256) {
                unsigned long long kk = ((unsigned long long)fkey(sv[i]) << 32)
                                      | (unsigned)(0xFFFFFFFFu - (unsigned)i);
                if (kk > nk) nk = kk;
            }
            mykey = nk;
        }
        if (warp == (owner >> 5)) {
            unsigned long long kk = mykey;
            #pragma unroll
            for (int o = 16; o; o >>= 1) {
                unsigned long long ot = __shfl_down_sync(0xffffffffu, kk, o);
                if (ot > kk) kk = ot;
            }
            if (lane == 0) wmax[warp] = kk;
        }
        __syncthreads();
    }

    // exact fp64 rescore: one warp per candidate, round-robin
    {
        double qd = fmax(sqrt(g_qn2[b]), 1e-12);
        for (int c = warp; c < NCAND; c += 8) {
            int idx = cidx[c];
            const float* mrow = Mem + (size_t)idx * D;
            double acc = 0.0;
            #pragma unroll 4
            for (int d = lane; d < D; d += 32)
                acc += (double)qs[d] * (double)mrow[d];
            #pragma unroll
            for (int o = 16; o; o >>= 1) acc += __shfl_down_sync(0xffffffffu, acc, o);
            if (lane == 0) {
                double md = fmax(sqrt(g_mn2[idx]), 1e-12);
                cval[c] = acc / (qd * md);
            }
        }
    }
    __syncthreads();

    int k = *kp;
    if (k > KMAX)  k = KMAX;
    if (k > NCAND) k = NCAND;
    if (k > M)     k = M;

    // top-k among candidates (fp64 desc, index asc); mask exact-match sims
    if (t == 0) {
        unsigned long long used = 0ull;
        for (int it = 0; it < k; it++) {
            double bv = -1e300;
            int bc = 0, bidx = 0x7fffffff;
            for (int c = 0; c < NCAND; c++) {
                if (used & (1ull << c)) continue;
                double v = cval[c];
                if ((float)v == 1.0f) v = -1.0/0.0;   // reference masks sim==1.0
                int ix = cidx[c];
                if (v > bv || (v == bv && ix < bidx)) { bv = v; bc = c; bidx = ix; }
            }
            used |= (1ull << bc);
            float wv = (float)bv;
            if (!isfinite(wv)) wv = 0.f;
            fw[it] = wv;
            fi[it] = bidx;
        }
    }
    __syncthreads();

    for (int d = t; d < D; d += 256) {
        float acc = 0.f;
        for (int j = 0; j < k; j++)
            acc += fw[j] * Mem[(size_t)fi[j] * D + d];
        out[(size_t)b * D + d] = acc;
    }
}

// ---------------------------------------------------------------------------
extern "C" void kernel_launch(void* const* d_in, const int* in_sizes, int n_in,
                              void* d_out, int out_size) {
    const float* q  = (const float*)d_in[0];
    const float* m  = (const float*)d_in[1];
    const int*   kp = (const int*)d_in[2];
    float* out = (float*)d_out;

    int B = in_sizes[0] / D;   // 4096
    int M = in_sizes[1] / D;   // 8192

    norms_kernel<<<B + M, 128>>>(q, m, B, M);
    convert_kernel<<<B + M, 256>>>(q, m, B, M);

    dim3 gg(M / BN, B / BM);
    hgemm_kernel<<<gg, 256>>>(B, M);

    topk_kernel<<<B, 256>>>(q, m, out, kp, B, M);
}